// round 1
// baseline (speedup 1.0000x reference)
#include <cuda_runtime.h>
#include <cstdint>

#define FULLMASK 0xffffffffu

// One warp per batch element. Lane L owns states (2L, 2L+1) as (mlo, mhi).
// Predecessors of 2L   = (4L)%64, (4L+1)%64 = (lo, hi) of lane (2L)&31.
// Predecessors of 2L+1 = (4L+2)%64,(4L+3)%64 = (lo, hi) of lane (2L+1)&31.
// W(s): 32-bit window of traceback-path decision bits from state s; snapshot
// every 32 steps for t >= 1024 -> traceback is 64 dependent shared loads.
__global__ void __launch_bounds__(128, 1) cva_kernel(const float* __restrict__ x,
                                                     float* __restrict__ out)
{
    extern __shared__ uint32_t snap_smem[];
    const int warp  = threadIdx.x >> 5;
    const int lane  = threadIdx.x & 31;
    const int batch = blockIdx.x * 4 + warp;
    uint32_t* snap = snap_smem + warp * 4096;   // 64 snapshots x 64 states

    const float2* xp = reinterpret_cast<const float2*>(x + (size_t)batch * 2048);

    // Lane-constant branch-code coefficients.
    // code bit0 (l0 coeff) = parity(s & 0x3C) ^ j ; code bit1 (l1 coeff) = parity(s & 0x2D) ^ j
    const int   sL = 2 * lane;
    const float eA = (float)(__popc(sL & 0x3C) & 1);   // l0 coeff, edge (2L, j=0)
    const float fA = (float)(__popc(sL & 0x2D) & 1);   // l1 coeff, edge (2L, j=0)
    const float eB = 1.0f - eA;
    const float fB = 1.0f - fA;
    const int src0 = (2 * lane) & 31;
    const int src1 = src0 + 1;

    float    mlo = 0.0f, mhi = 0.0f;   // path metrics (in_prob0 = 0)
    uint32_t Wlo = 0u,   Whi = 0u;     // decision windows

    for (int ch = 0; ch < 96; ++ch) {
        // llr pair for step t is x2[b][t % 1024]; chunk never wraps (32 | 1024)
        float2 p = xp[((ch & 31) << 5) + lane];

        #pragma unroll 8
        for (int i = 0; i < 32; ++i) {
            float l0 = __shfl_sync(FULLMASK, p.x, i);
            float l1 = __shfl_sync(FULLMASK, p.y, i);

            float a0 = __shfl_sync(FULLMASK, mlo, src0);  // m[(4L)%64]
            float a1 = __shfl_sync(FULLMASK, mhi, src0);  // m[(4L+1)%64]
            float b0 = __shfl_sync(FULLMASK, mlo, src1);  // m[(4L+2)%64]
            float b1 = __shfl_sync(FULLMASK, mhi, src1);  // m[(4L+3)%64]

            uint32_t wa0 = __shfl_sync(FULLMASK, Wlo, src0);
            uint32_t wa1 = __shfl_sync(FULLMASK, Whi, src0);
            uint32_t wb0 = __shfl_sync(FULLMASK, Wlo, src1);
            uint32_t wb1 = __shfl_sync(FULLMASK, Whi, src1);

            // Branch metrics: exact single-rounding of l0*c0 + l1*c1
            float qa  = l0 * eA;
            float qb  = l0 * eB;
            float bm0 = fmaf(l1, fA, qa);   // edge (2L,   j=0) : code X
            float bm1 = fmaf(l1, fB, qb);   // edge (2L,   j=1) : code X^3
            float bm2 = fmaf(l1, fB, qa);   // edge (2L+1, j=0) : code X^2
            float bm3 = fmaf(l1, fA, qb);   // edge (2L+1, j=1) : code X^1

            float t0l = a0 + bm0;
            float t1l = a1 + bm1;
            float t0h = b0 + bm2;
            float t1h = b1 + bm3;

            bool jl = (t1l < t0l);          // argmin tie -> j=0, matches jnp.argmin
            bool jh = (t1h < t0h);

            float vl = fminf(t0l, t1l);
            float vh = fminf(t0h, t1h);
            mlo = fmaxf(fminf(vl, 20.0f), -20.0f);
            mhi = fmaxf(fminf(vh, 20.0f), -20.0f);

            Wlo = ((jl ? wa1 : wa0) << 1) | (uint32_t)jl;
            Whi = ((jh ? wb1 : wb0) << 1) | (uint32_t)jh;
        }

        if (ch >= 32) {                      // snapshots cover t in [1024, 3072)
            int c = ch - 32;                 // 0..63
            *reinterpret_cast<uint2*>(&snap[(c << 6) + sL]) = make_uint2(Wlo, Whi);
        }
    }

    __syncwarp();

    // Traceback: start state 0 at t=3072; each hop consumes one 32-bit window.
    // snapshot c has t_last = 32c + 1055; w bit i = j_{t_last - i} along path.
    // output bit_tau = 1 - j_{tau+1}; needed tau in [1024, 2047].
    float* orow = out + (size_t)batch * 1024;
    int s = 0;
    for (int c = 63; c >= 0; --c) {
        uint32_t w = snap[(c << 6) + s];     // same addr all lanes: LDS broadcast
        if (c <= 32) {
            int idx = (c << 5) + 30 - lane;  // = (t_last - lane - 1) - 1024
            if ((unsigned)idx < 1024u) {
                orow[idx] = ((w >> lane) & 1u) ? 0.0f : 1.0f;
            }
        }
        s = (int)(__brev(w) & 63u);          // state 32 steps earlier
    }
}

extern "C" void kernel_launch(void* const* d_in, const int* in_sizes, int n_in,
                              void* d_out, int out_size)
{
    const float* x = (const float*)d_in[0];
    float* out = (float*)d_out;
    cudaFuncSetAttribute(cva_kernel, cudaFuncAttributeMaxDynamicSharedMemorySize, 65536);
    cva_kernel<<<128, 128, 65536>>>(x, out);
}